// round 3
// baseline (speedup 1.0000x reference)
#include <cuda_runtime.h>
#include <cuda_bf16.h>

// TripletSemihardLoss, fully fused single-launch version.
// N x D f32 embeddings, N labels (int32 or int64, autodetected in-kernel).
//
// Each block owns R=4 anchor rows i. It recomputes its own distance rows
//   d[i,j] = sqrt(max(sq_i + sq_j - 2*e_i.e_j, EPS))
// (sq_j computed in the same pass), then does the semi-hard reduction for its
// rows, writes a (num,den) partial, and the last block (atomic ticket)
// combines partials and writes the scalar. No grid sync, one kernel launch.

#define EPSV    1e-4f
#define MARGINV 1.0f
#define R       4
#define TPB     512
#define NWARP   (TPB / 32)
#define MAXN    512
#define MAXD    256
#define MAXBLK  (MAXN / R)

__device__ float        g_part[2 * MAXBLK];
__device__ unsigned int g_count;          // zero-init; last block resets to 0

__global__ void __launch_bounds__(TPB)
fused_triplet(const float* __restrict__ emb,
              const unsigned int* __restrict__ labs,
              float* __restrict__ out,
              int N, int D, int nblocks) {
    __shared__ int   labs_s[MAXN];
    __shared__ __align__(16) float es[R][MAXD];   // this block's anchor rows
    __shared__ float sqi[R];
    __shared__ float r_s[R][MAXN];                // distance rows
    __shared__ float s_mx[R], s_mn[R];
    __shared__ float wred_mx[R][NWARP], wred_mn[R][NWARP];
    __shared__ float wsum[NWARP];
    __shared__ int   wden[NWARP];
    __shared__ int   s_is64;

    const int tid  = threadIdx.x;
    const int lane = tid & 31;
    const int warp = tid >> 5;
    const int i0   = blockIdx.x * R;
    const int D4   = D >> 2;

    // ---- label dtype detection (int64 => odd 32-bit LE words are 0) ----
    if (tid == 0) {
        int is64 = 1;
        for (int w = 1; w < 16; w += 2)
            if (labs[w] != 0u) is64 = 0;
        s_is64 = is64;
    }
    __syncthreads();
    const int is64 = s_is64;

    // ---- load labels + anchor rows ----
    for (int j = tid; j < N; j += TPB)
        labs_s[j] = (int)labs[is64 ? 2 * j : j];
    for (int e = tid; e < R * D; e += TPB) {
        int t = e / D, c = e % D;
        int gi = i0 + t;
        es[t][c] = (gi < N) ? emb[(size_t)gi * D + c] : 0.0f;
    }
    __syncthreads();

    // ---- sq of anchor rows (warp t handles row t) ----
    if (warp < R) {
        float s = 0.0f;
        for (int c = lane; c < D; c += 32) {
            float v = es[warp][c];
            s = fmaf(v, v, s);
        }
        #pragma unroll
        for (int o = 16; o > 0; o >>= 1)
            s += __shfl_down_sync(0xffffffffu, s, o);
        if (lane == 0) sqi[warp] = s;
    }
    __syncthreads();

    // ---- phase B: distance rows. warp-per-j; 5 dots per j (sq_j + R anchors) ----
    for (int j = warp; j < N; j += NWARP) {
        const float4* rowj = (const float4*)(emb + (size_t)j * D);
        float sqj = 0.0f;
        float dt0 = 0.0f, dt1 = 0.0f, dt2 = 0.0f, dt3 = 0.0f;
        for (int c4 = lane; c4 < D4; c4 += 32) {
            float4 v = rowj[c4];
            sqj = fmaf(v.x, v.x, fmaf(v.y, v.y, fmaf(v.z, v.z, fmaf(v.w, v.w, sqj))));
            float4 w0 = ((const float4*)es[0])[c4];
            dt0 = fmaf(v.x, w0.x, fmaf(v.y, w0.y, fmaf(v.z, w0.z, fmaf(v.w, w0.w, dt0))));
            float4 w1 = ((const float4*)es[1])[c4];
            dt1 = fmaf(v.x, w1.x, fmaf(v.y, w1.y, fmaf(v.z, w1.z, fmaf(v.w, w1.w, dt1))));
            float4 w2 = ((const float4*)es[2])[c4];
            dt2 = fmaf(v.x, w2.x, fmaf(v.y, w2.y, fmaf(v.z, w2.z, fmaf(v.w, w2.w, dt2))));
            float4 w3 = ((const float4*)es[3])[c4];
            dt3 = fmaf(v.x, w3.x, fmaf(v.y, w3.y, fmaf(v.z, w3.z, fmaf(v.w, w3.w, dt3))));
        }
        #pragma unroll
        for (int o = 16; o > 0; o >>= 1) {
            sqj += __shfl_down_sync(0xffffffffu, sqj, o);
            dt0 += __shfl_down_sync(0xffffffffu, dt0, o);
            dt1 += __shfl_down_sync(0xffffffffu, dt1, o);
            dt2 += __shfl_down_sync(0xffffffffu, dt2, o);
            dt3 += __shfl_down_sync(0xffffffffu, dt3, o);
        }
        if (lane == 0) {
            float dts[R] = {dt0, dt1, dt2, dt3};
            #pragma unroll
            for (int t = 0; t < R; t++) {
                float v = (sqi[t] + sqj) - 2.0f * dts[t];
                v = fmaxf(v, 0.0f);
                v = fmaxf(v, EPSV);
                r_s[t][j] = sqrtf(v);
            }
        }
    }
    __syncthreads();

    // ---- per-row min/max of the distance rows ----
    {
        float lmx[R], lmn[R];
        #pragma unroll
        for (int t = 0; t < R; t++) { lmx[t] = -1e30f; lmn[t] = 1e30f; }
        for (int j = tid; j < N; j += TPB) {
            #pragma unroll
            for (int t = 0; t < R; t++) {
                float v = r_s[t][j];
                lmx[t] = fmaxf(lmx[t], v);
                lmn[t] = fminf(lmn[t], v);
            }
        }
        #pragma unroll
        for (int o = 16; o > 0; o >>= 1) {
            #pragma unroll
            for (int t = 0; t < R; t++) {
                lmx[t] = fmaxf(lmx[t], __shfl_down_sync(0xffffffffu, lmx[t], o));
                lmn[t] = fminf(lmn[t], __shfl_down_sync(0xffffffffu, lmn[t], o));
            }
        }
        if (lane == 0) {
            #pragma unroll
            for (int t = 0; t < R; t++) {
                wred_mx[t][warp] = lmx[t];
                wred_mn[t][warp] = lmn[t];
            }
        }
        __syncthreads();
        if (tid < R) {
            float mx = wred_mx[tid][0], mn = wred_mn[tid][0];
            for (int w = 1; w < NWARP; w++) {
                mx = fmaxf(mx, wred_mx[tid][w]);
                mn = fminf(mn, wred_mn[tid][w]);
            }
            s_mx[tid] = mx;
            s_mn[tid] = mn;
        }
        __syncthreads();
    }

    // ---- loss: deterministic (t,k) job striding over warps ----
    float warpsum = 0.0f;
    int   warpden = 0;
    for (int job = warp; job < R * N; job += NWARP) {
        const int t = job / N;
        const int k = job - t * N;
        const int gi = i0 + t;
        if (gi >= N) continue;
        const int lt = labs_s[gi];
        if (!(labs_s[k] == lt && k != gi)) continue;   // only positive pairs

        const float c     = r_s[t][k];
        const float mn_dd = c - s_mx[t];   // == min_j fl(c - r_j)  (monotone rounding)
        const float mx_dd = c - s_mn[t];   // == max_j fl(c - r_j)
        float m1 = 0.0f, m2 = 0.0f;
        unsigned anyv = 0u;
        for (int j = lane; j < N; j += 32) {
            float dd = c - r_s[t][j];
            int same = (labs_s[j] == lt) && (j != gi);  // pos[i,j]
            int Mj = !same;                              // 1 - pos (incl. j==i)
            int maskj = Mj && (dd < 0.0f);
            anyv |= (unsigned)maskj;
            m1 = fmaxf(m1, maskj ? (dd - mn_dd) : 0.0f);
            m2 = fminf(m2, Mj    ? (dd - mx_dd) : 0.0f);
        }
        anyv = __any_sync(0xffffffffu, anyv);
        #pragma unroll
        for (int o = 16; o > 0; o >>= 1) {
            m1 = fmaxf(m1, __shfl_down_sync(0xffffffffu, m1, o));
            m2 = fminf(m2, __shfl_down_sync(0xffffffffu, m2, o));
        }
        if (lane == 0) {
            float semi = anyv ? (m1 + mn_dd) : (m2 + mx_dd);
            warpsum += fmaxf(semi + MARGINV, 0.0f);
            warpden += 1;
        }
    }
    if (lane == 0) { wsum[warp] = warpsum; wden[warp] = warpden; }
    __syncthreads();

    // ---- block partial (deterministic sequential combine) + last-block finish ----
    if (tid == 0) {
        float num = 0.0f;
        int   den = 0;
        for (int w = 0; w < NWARP; w++) { num += wsum[w]; den += wden[w]; }
        g_part[2 * blockIdx.x]     = num;
        g_part[2 * blockIdx.x + 1] = (float)den;
        __threadfence();
        unsigned int ticket = atomicAdd(&g_count, 1u);
        if (ticket == (unsigned int)(nblocks - 1)) {
            float tnum = 0.0f, tden = 0.0f;
            for (int b = 0; b < nblocks; b++) {
                tnum += g_part[2 * b];
                tden += g_part[2 * b + 1];
            }
            out[0] = tnum / tden;
            g_count = 0;   // reset for next graph replay
        }
    }
}

extern "C" void kernel_launch(void* const* d_in, const int* in_sizes, int n_in,
                              void* d_out, int out_size) {
    const float* emb = (const float*)d_in[0];
    const unsigned int* labs = (const unsigned int*)d_in[1];
    float* out = (float*)d_out;

    const int N = in_sizes[1];
    const int D = in_sizes[0] / N;
    const int nblocks = (N + R - 1) / R;

    fused_triplet<<<nblocks, TPB>>>(emb, labs, out, N, D, nblocks);
}

// round 4
// speedup vs baseline: 2.1497x; 2.1497x over previous
#include <cuda_runtime.h>
#include <cuda_bf16.h>

// TripletSemihardLoss — single launch.
// Phase 1: all blocks compute 32x32 tiles of the distance matrix (GEMM-style).
// Global software barrier (all blocks co-resident: grid <= #SMs).
// Phase 2: warp-per-anchor-row semi-hard loss; ticket finisher writes scalar.

#define EPSV    1e-4f
#define MARGINV 1.0f
#define TILE    32
#define TPB     256
#define CHUNK   128
#define MAXN    512

__device__ float    g_d[MAXN * MAXN];
__device__ float    g_acc[2];          // zero-init; finisher resets
__device__ unsigned g_bar;             // barrier counter
__device__ unsigned g_done;            // finish ticket

__global__ void __launch_bounds__(TPB)
triplet_all(const float* __restrict__ emb,
            const unsigned int* __restrict__ labs,
            float* __restrict__ out,
            int N, int D, int nblocks) {
    __shared__ __align__(16) float As[TILE][CHUNK + 4];
    __shared__ __align__(16) float Bs[TILE][CHUNK + 4];
    __shared__ float sqA_s[TILE], sqB_s[TILE];
    __shared__ int   s_is64;

    const int tid  = threadIdx.x;
    const int lane = tid & 31;
    const int warp = tid >> 5;
    const int tx   = tid & 15;          // col pair (tx, tx+16)
    const int ty   = tid >> 4;          // row pair (ty, ty+16)
    const int bx   = blockIdx.x;
    const int by   = blockIdx.y;
    const int GX   = gridDim.x;

    if (tid == 0) {
        int is64 = 1;
        for (int w = 1; w < 16; w += 2)
            if (labs[w] != 0u) is64 = 0;
        s_is64 = is64;
    }

    // ================= Phase 1: distance tile (by*32.., bx*32..) ============
    float acc00 = 0.f, acc01 = 0.f, acc10 = 0.f, acc11 = 0.f;
    float sqacc = 0.f;   // threads 0..63 accumulate row norms

    for (int kk = 0; kk < D; kk += CHUNK) {
        // cooperative float4 tile loads (zero-filled out of range)
        const int NC4 = CHUNK / 4;
        for (int e = tid; e < TILE * NC4; e += TPB) {
            int r = e / NC4, c4 = e % NC4;
            int gc = kk + c4 * 4;
            float4 va = make_float4(0.f, 0.f, 0.f, 0.f);
            float4 vb = make_float4(0.f, 0.f, 0.f, 0.f);
            int ga = by * TILE + r;
            int gb = bx * TILE + r;
            if (ga < N && gc + 3 < D)
                va = *(const float4*)(emb + (size_t)ga * D + gc);
            if (gb < N && gc + 3 < D)
                vb = *(const float4*)(emb + (size_t)gb * D + gc);
            *(float4*)&As[r][c4 * 4] = va;
            *(float4*)&Bs[r][c4 * 4] = vb;
        }
        __syncthreads();

        // row squared norms: threads 0..31 -> A rows, 32..63 -> B rows
        if (tid < 64) {
            const float* src = (tid < 32) ? As[tid] : Bs[tid - 32];
            float s = sqacc;
            #pragma unroll 4
            for (int c = 0; c < CHUNK; c++) {
                float v = src[c];
                s = fmaf(v, v, s);
            }
            sqacc = s;
        }

        // Gram: 2x2 register tile, float4 smem reads
        #pragma unroll 8
        for (int c4 = 0; c4 < NC4; c4++) {
            float4 a0 = *(const float4*)&As[ty][c4 * 4];
            float4 a1 = *(const float4*)&As[ty + 16][c4 * 4];
            float4 b0 = *(const float4*)&Bs[tx][c4 * 4];
            float4 b1 = *(const float4*)&Bs[tx + 16][c4 * 4];
            acc00 = fmaf(a0.x, b0.x, fmaf(a0.y, b0.y, fmaf(a0.z, b0.z, fmaf(a0.w, b0.w, acc00))));
            acc01 = fmaf(a0.x, b1.x, fmaf(a0.y, b1.y, fmaf(a0.z, b1.z, fmaf(a0.w, b1.w, acc01))));
            acc10 = fmaf(a1.x, b0.x, fmaf(a1.y, b0.y, fmaf(a1.z, b0.z, fmaf(a1.w, b0.w, acc10))));
            acc11 = fmaf(a1.x, b1.x, fmaf(a1.y, b1.y, fmaf(a1.z, b1.z, fmaf(a1.w, b1.w, acc11))));
        }
        __syncthreads();
    }

    if (tid < 32)       sqA_s[tid]      = sqacc;
    else if (tid < 64)  sqB_s[tid - 32] = sqacc;
    __syncthreads();

    // write d tile
    {
        const int rows[2] = { ty, ty + 16 };
        const int cols[2] = { tx, tx + 16 };
        float accs[2][2] = { {acc00, acc01}, {acc10, acc11} };
        #pragma unroll
        for (int a = 0; a < 2; a++) {
            int gr = by * TILE + rows[a];
            if (gr >= N) continue;
            #pragma unroll
            for (int b = 0; b < 2; b++) {
                int gc = bx * TILE + cols[b];
                if (gc >= N) continue;
                float v = (sqA_s[rows[a]] + sqB_s[cols[b]]) - 2.0f * accs[a][b];
                v = fmaxf(v, 0.0f);
                v = fmaxf(v, EPSV);
                g_d[gr * N + gc] = sqrtf(v);
            }
        }
    }

    // ================= global software barrier ===============================
    __threadfence();
    __syncthreads();
    if (tid == 0) {
        atomicAdd(&g_bar, 1u);
        while (atomicAdd(&g_bar, 0u) < (unsigned)nblocks)
            __nanosleep(64);
    }
    __syncthreads();
    __threadfence();

    // ================= Phase 2: warp-per-anchor-row loss =====================
    const int is64 = s_is64;
    const int bid  = by * GX + bx;
    const int gw   = bid * (TPB / 32) + warp;   // global warp id

    float warpsum = 0.0f;
    int   warpden = 0;

    if (gw < N) {
        const int i = gw;
        const float* __restrict__ row = g_d + (size_t)i * N;
        const int li = (int)labs[is64 ? 2 * i : i];

        // row min/max (butterfly -> all lanes)
        float lmx = -1e30f, lmn = 1e30f;
        for (int j = lane; j < N; j += 32) {
            float v = __ldg(row + j);
            lmx = fmaxf(lmx, v);
            lmn = fminf(lmn, v);
        }
        #pragma unroll
        for (int o = 16; o > 0; o >>= 1) {
            lmx = fmaxf(lmx, __shfl_xor_sync(0xffffffffu, lmx, o));
            lmn = fminf(lmn, __shfl_xor_sync(0xffffffffu, lmn, o));
        }
        const float mx_d = lmx, mn_d = lmn;

        // enumerate positives k via ballot, then warp-scan each pair
        const int niter = (N + 31) >> 5;
        for (int it = 0; it < niter; it++) {
            int j = it * 32 + lane;
            int isp = 0;
            if (j < N) {
                int lj = (int)labs[is64 ? 2 * j : j];
                isp = (lj == li) && (j != i);
            }
            unsigned bm = __ballot_sync(0xffffffffu, isp);
            while (bm) {
                int b = __ffs(bm) - 1;
                bm &= bm - 1;
                const int k = it * 32 + b;

                const float c     = __ldg(row + k);
                const float mn_dd = c - mx_d;   // == min_j fl(c - d_j) (monotone)
                const float mx_dd = c - mn_d;   // == max_j fl(c - d_j)
                float m1 = 0.0f, m2 = 0.0f;
                unsigned anyv = 0u;
                for (int jj = lane; jj < N; jj += 32) {
                    float dd = c - __ldg(row + jj);
                    int lj2 = (int)labs[is64 ? 2 * jj : jj];
                    int same = (lj2 == li) && (jj != i);     // pos[i,jj]
                    int Mj = !same;                           // 1 - pos (incl jj==i)
                    int maskj = Mj && (dd < 0.0f);
                    anyv |= (unsigned)maskj;
                    m1 = fmaxf(m1, maskj ? (dd - mn_dd) : 0.0f);
                    m2 = fminf(m2, Mj    ? (dd - mx_dd) : 0.0f);
                }
                anyv = __any_sync(0xffffffffu, anyv);
                #pragma unroll
                for (int o = 16; o > 0; o >>= 1) {
                    m1 = fmaxf(m1, __shfl_down_sync(0xffffffffu, m1, o));
                    m2 = fminf(m2, __shfl_down_sync(0xffffffffu, m2, o));
                }
                if (lane == 0) {
                    float semi = anyv ? (m1 + mn_dd) : (m2 + mx_dd);
                    warpsum += fmaxf(semi + MARGINV, 0.0f);
                    warpden += 1;
                }
            }
        }
    }

    if (lane == 0 && warpden > 0) {
        atomicAdd(&g_acc[0], warpsum);
        atomicAdd(&g_acc[1], (float)warpden);
    }

    // ================= finisher ==============================================
    __syncthreads();
    __threadfence();
    if (tid == 0) {
        unsigned t = atomicAdd(&g_done, 1u);
        if (t == (unsigned)(nblocks - 1)) {
            float num = atomicAdd(&g_acc[0], 0.0f);
            float den = atomicAdd(&g_acc[1], 0.0f);
            out[0] = num / den;
            atomicExch(&g_acc[0], 0.0f);
            atomicExch(&g_acc[1], 0.0f);
            atomicExch(&g_bar, 0u);
            atomicExch(&g_done, 0u);
            __threadfence();
        }
    }
}

extern "C" void kernel_launch(void* const* d_in, const int* in_sizes, int n_in,
                              void* d_out, int out_size) {
    const float* emb = (const float*)d_in[0];
    const unsigned int* labs = (const unsigned int*)d_in[1];
    float* out = (float*)d_out;

    const int N = in_sizes[1];
    const int D = in_sizes[0] / N;
    const int G = (N + TILE - 1) / TILE;

    dim3 grid(G, G);
    triplet_all<<<grid, TPB>>>(emb, labs, out, N, D, G * G);
}

// round 7
// speedup vs baseline: 2.1832x; 1.0156x over previous
#include <cuda_runtime.h>
#include <cuda_bf16.h>

// TripletSemihardLoss — single launch, block-local everything.
// Block b owns R=4 anchor rows. Phase 1: its 4 distance rows via a staged
// transposed tile GEMM (thread-per-column, warp-uniform anchor broadcasts).
// Phase 2: semi-hard loss via successor queries on the smem rows.
// Deterministic block partials + ticket-elected finisher.

#define EPSV    1e-4f
#define MARGINV 1.0f
#define TPB     384
#define NWARP   (TPB / 32)
#define R       4
#define MAXP    64
#define NJ      384          // max columns (N <= NJ)
#define BS4     385          // padded j-stride
#define NG      4            // float4 groups per chunk (16 c-values)
#define MAXBLK  128

__device__ float    g_part[2 * MAXBLK];
__device__ unsigned g_done;   // zero-init; finisher resets

__global__ void __launch_bounds__(TPB, 1)
triplet_fused(const float* __restrict__ emb,
              const unsigned int* __restrict__ labs,
              float* __restrict__ out,
              int N, int D, int nblocks) {
    __shared__ __align__(16) float4 Bst4[NG][BS4];  // 16 c-values x 384 j
    __shared__ float r_s[R][BS4];                   // distance rows
    __shared__ int   labs_s[NJ];
    __shared__ int   plist[R][MAXP];
    __shared__ float s_sqa[R], s_mn[R], s_mx[R], s_mxneg[R];
    __shared__ int   s_cnt[R], s_li[R];
    __shared__ float wsum[NWARP];
    __shared__ int   s_is64;

    const int tid  = threadIdx.x;
    const int lane = tid & 31;
    const int warp = tid >> 5;
    const int i0   = blockIdx.x * R;
    const int D4   = D >> 2;
    const int nch  = D4 / NG;        // chunks of 16 c-values

    if (tid == 0) {
        int is64 = 1;
        for (int w = 1; w < 16; w += 2)
            if (labs[w] != 0u) is64 = 0;
        s_is64 = is64;
    }
    __syncthreads();
    const int is64 = s_is64;

    // labels to smem (sentinel for padding columns)
    labs_s[tid] = (tid < N) ? (int)labs[is64 ? 2 * tid : tid] : 0x7fffffff;

    // ================= Phase 1: 4 distance rows via staged GEMM ==============
    const float4* __restrict__ gsrc = (const float4*)emb;
    float acc0 = 0.f, acc1 = 0.f, acc2 = 0.f, acc3 = 0.f, sq = 0.f;
    float4 st[NG];

    // prefetch chunk 0
    #pragma unroll
    for (int p = 0; p < NG; p++) {
        int idx = p * TPB + tid;
        int g = idx & (NG - 1), j = idx >> 2;
        st[p] = (j < N) ? __ldg(&gsrc[(size_t)j * D4 + g])
                        : make_float4(0.f, 0.f, 0.f, 0.f);
    }

    for (int ch = 0; ch < nch; ch++) {
        #pragma unroll
        for (int p = 0; p < NG; p++) {
            int idx = p * TPB + tid;
            int g = idx & (NG - 1), j = idx >> 2;
            Bst4[g][j] = st[p];
        }
        __syncthreads();

        // prefetch next chunk while computing this one
        if (ch + 1 < nch) {
            #pragma unroll
            for (int p = 0; p < NG; p++) {
                int idx = p * TPB + tid;
                int g = idx & (NG - 1), j = idx >> 2;
                st[p] = (j < N) ? __ldg(&gsrc[(size_t)j * D4 + (ch + 1) * NG + g])
                                : make_float4(0.f, 0.f, 0.f, 0.f);
            }
        }

        // thread owns column j = tid; anchors are warp-uniform broadcasts
        #pragma unroll
        for (int g = 0; g < NG; g++) {
            float4 v  = Bst4[g][tid];
            float4 a0 = Bst4[g][i0 + 0];
            float4 a1 = Bst4[g][i0 + 1];
            float4 a2 = Bst4[g][i0 + 2];
            float4 a3 = Bst4[g][i0 + 3];
            acc0 = fmaf(a0.x, v.x, fmaf(a0.y, v.y, fmaf(a0.z, v.z, fmaf(a0.w, v.w, acc0))));
            acc1 = fmaf(a1.x, v.x, fmaf(a1.y, v.y, fmaf(a1.z, v.z, fmaf(a1.w, v.w, acc1))));
            acc2 = fmaf(a2.x, v.x, fmaf(a2.y, v.y, fmaf(a2.z, v.z, fmaf(a2.w, v.w, acc2))));
            acc3 = fmaf(a3.x, v.x, fmaf(a3.y, v.y, fmaf(a3.z, v.z, fmaf(a3.w, v.w, acc3))));
            sq   = fmaf(v.x,  v.x, fmaf(v.y,  v.y, fmaf(v.z,  v.z, fmaf(v.w,  v.w, sq))));
        }
        __syncthreads();
    }

    // anchor squared norms: thread i0+t owns column i0+t -> its sq IS sq_anchor
    if (tid >= i0 && tid < i0 + R && tid < N) s_sqa[tid - i0] = sq;
    if (warp == 0 && lane < R) {
        int gi = i0 + lane;
        s_li[lane] = (gi < N) ? labs_s[gi] : 0x80000000;
    }
    __syncthreads();

    // distance rows to smem
    if (tid < N) {
        float accs[R] = { acc0, acc1, acc2, acc3 };
        #pragma unroll
        for (int t = 0; t < R; t++) {
            int gi = i0 + t;
            if (gi < N) {
                float v = (s_sqa[t] + sq) - 2.0f * accs[t];
                v = fmaxf(v, 0.0f);
                v = fmaxf(v, EPSV);
                r_s[t][tid] = sqrtf(v);
            }
        }
    }
    __syncthreads();

    // ================= Phase 2a: per-row stats + positive list ==============
    if (warp < R) {
        const int t  = warp;
        const int gi = i0 + t;
        float mn = 1e30f, mx = -1e30f, mxneg = -1e30f;
        int cnt = 0;
        if (gi < N) {
            const int li = s_li[t];
            const unsigned lmlt = (1u << lane) - 1u;
            for (int jb = 0; jb < NJ; jb += 32) {
                int j = jb + lane;
                bool val = (j < N);
                float r = val ? r_s[t][j] : 0.0f;
                bool pos = val && (labs_s[j] == li) && (j != gi);
                if (val) {
                    mn = fminf(mn, r);
                    mx = fmaxf(mx, r);
                    if (!pos) mxneg = fmaxf(mxneg, r);  // negatives incl. diagonal
                }
                unsigned bm = __ballot_sync(0xffffffffu, pos);
                if (pos) {
                    int o = cnt + __popc(bm & lmlt);
                    if (o < MAXP) plist[t][o] = j;
                }
                cnt += __popc(bm);
            }
            if (cnt > MAXP) cnt = MAXP;
            #pragma unroll
            for (int o = 16; o > 0; o >>= 1) {
                mn    = fminf(mn,    __shfl_xor_sync(0xffffffffu, mn,    o));
                mx    = fmaxf(mx,    __shfl_xor_sync(0xffffffffu, mx,    o));
                mxneg = fmaxf(mxneg, __shfl_xor_sync(0xffffffffu, mxneg, o));
            }
        }
        if (lane == 0) {
            s_mn[t] = mn; s_mx[t] = mx; s_mxneg[t] = mxneg; s_cnt[t] = cnt;
        }
    }
    __syncthreads();

    // ================= Phase 2b: successor query per positive pair ==========
    float mysum = 0.0f;
    for (int idx = warp; idx < R * MAXP; idx += NWARP) {
        const int t = idx >> 6;          // MAXP = 64
        const int p = idx & (MAXP - 1);
        if (p >= s_cnt[t]) continue;
        const int gi = i0 + t;
        const int li = s_li[t];
        const int k  = plist[t][p];
        const float c = r_s[t][k];

        // succ = min { r_j : j negative, r_j > c }  (argmax of masked dd = c - r)
        float succ = 1e30f;
        for (int jb = 0; jb < NJ; jb += 32) {
            int j = jb + lane;
            if (j < N) {
                float r = r_s[t][j];
                bool neg = (labs_s[j] != li) || (j == gi);
                if (neg && (r > c)) succ = fminf(succ, r);
            }
        }
        #pragma unroll
        for (int o = 16; o > 0; o >>= 1)
            succ = fminf(succ, __shfl_xor_sync(0xffffffffu, succ, o));

        if (lane == 0) {
            float semi;
            if (succ < 1e29f) {
                // reference: masked_maximum over dd = (dd - mn_dd) max, + mn_dd
                float mn_dd = c - s_mx[t];          // == min_j fl(c - r_j)
                float dd    = c - succ;
                semi = (dd - mn_dd) + mn_dd;        // replicate rounding
            } else {
                float mx_dd = c - s_mn[t];          // == max_j fl(c - r_j)
                float dd    = c - s_mxneg[t];
                semi = (dd - mx_dd) + mx_dd;
            }
            mysum += fmaxf(semi + MARGINV, 0.0f);
        }
    }
    if (lane == 0) wsum[warp] = mysum;
    __syncthreads();

    // ================= block partial + ticket finisher =======================
    if (tid == 0) {
        float num = 0.0f;
        for (int w = 0; w < NWARP; w++) num += wsum[w];
        int den = 0;
        #pragma unroll
        for (int t = 0; t < R; t++) den += s_cnt[t];
        g_part[2 * blockIdx.x]     = num;
        g_part[2 * blockIdx.x + 1] = (float)den;
        __threadfence();
        unsigned tk = atomicAdd(&g_done, 1u);
        if (tk == (unsigned)(nblocks - 1)) {
            volatile float* gp = g_part;
            float tn = 0.0f, td = 0.0f;
            for (int b = 0; b < nblocks; b++) {
                tn += gp[2 * b];
                td += gp[2 * b + 1];
            }
            out[0] = tn / td;
            g_done = 0;                 // reset for next graph replay
            __threadfence();
        }
    }
}

extern "C" void kernel_launch(void* const* d_in, const int* in_sizes, int n_in,
                              void* d_out, int out_size) {
    const float* emb = (const float*)d_in[0];
    const unsigned int* labs = (const unsigned int*)d_in[1];
    float* out = (float*)d_out;

    const int N = in_sizes[1];
    const int D = in_sizes[0] / N;
    const int nblocks = (N + R - 1) / R;

    triplet_fused<<<nblocks, TPB>>>(emb, labs, out, N, D, nblocks);
}

// round 8
// speedup vs baseline: 2.9903x; 1.3696x over previous
#include <cuda_runtime.h>
#include <cuda_bf16.h>

// TripletSemihardLoss — single launch, two phases + software grid barrier.
// Phase 1: 144 blocks (12x12) compute 32x32 distance-matrix tiles with a
//          2x2-microtile smem GEMM using packed fma.rn.f32x2.
// Phase 2: warp-per-anchor-row loss with the row held in registers;
//          successor-query reconstruction of the reference's masked max/min.
// Grid <= #SMs -> all blocks co-resident -> spin barrier is safe.

#define EPSV    1e-4f
#define MARGINV 1.0f
#define TILE    32
#define TPB     256
#define MAXN    512
#define NRMAX   12          // 12 * 32 = 384 row elements in registers

__device__ float    g_d[MAXN * MAXN];
__device__ float    g_num;      // zero-init; finisher resets
__device__ unsigned g_den;
__device__ unsigned g_bar;
__device__ unsigned g_done;

__device__ __forceinline__ void fma2(unsigned long long& d,
                                     unsigned long long a,
                                     unsigned long long b) {
    // packed f32x2 FMA: d.lo += a.lo*b.lo ; d.hi += a.hi*b.hi  (SASS FFMA2)
    asm("fma.rn.f32x2 %0, %1, %2, %0;" : "+l"(d) : "l"(a), "l"(b));
}

__global__ void __launch_bounds__(TPB, 1)
triplet_one(const float* __restrict__ emb,
            const unsigned int* __restrict__ labs,
            float* __restrict__ out,
            int N, int D, int nblocks) {
    __shared__ __align__(16) float As[TILE][132];   // 132-float stride: LDS.128
    __shared__ __align__(16) float Bs[TILE][132];   // phase-conflict-free
    __shared__ float sqA[TILE], sqB[TILE];
    __shared__ int   labs_s[MAXN];
    __shared__ int   s_is64;

    const int tid  = threadIdx.x;
    const int lane = tid & 31;
    const int warp = tid >> 5;
    const int tx   = tid & 15;          // col pair (tx, tx+16)
    const int ty   = tid >> 4;          // row pair (ty, ty+16)
    const int bx   = blockIdx.x;
    const int by   = blockIdx.y;

    if (tid == 0) {
        int e = 1;
        for (int w = 1; w < 16; w += 2)
            if (labs[w] != 0u) e = 0;
        s_is64 = e;
    }
    __syncthreads();
    const int is64 = s_is64;

    for (int j = tid; j < N; j += TPB)
        labs_s[j] = (int)labs[is64 ? 2 * j : j];

    // ---- tile loads: 32 rows x 128 cols each (zero-padded) ----
    for (int e = tid; e < TILE * 32; e += TPB) {
        int r = e >> 5, c4 = e & 31, gc = c4 * 4;
        int ga = by * TILE + r, gb = bx * TILE + r;
        float4 z = make_float4(0.f, 0.f, 0.f, 0.f);
        float4 va = (ga < N && gc + 3 < D) ? *(const float4*)(emb + (size_t)ga * D + gc) : z;
        float4 vb = (gb < N && gc + 3 < D) ? *(const float4*)(emb + (size_t)gb * D + gc) : z;
        *(float4*)&As[r][gc] = va;
        *(float4*)&Bs[r][gc] = vb;
    }
    __syncthreads();

    // ---- row squared norms: 8 warps x 8 rows ----
    #pragma unroll
    for (int q = 0; q < 8; q++) {
        int rr = warp * 8 + q;
        const float* src = (rr < 32) ? As[rr] : Bs[rr - 32];
        float s = 0.f;
        #pragma unroll
        for (int k = 0; k < 4; k++) {
            int c = lane + 32 * k;
            float v = (c < D) ? src[c] : 0.f;
            s = fmaf(v, v, s);
        }
        #pragma unroll
        for (int o = 16; o > 0; o >>= 1)
            s += __shfl_xor_sync(0xffffffffu, s, o);
        if (lane == 0) { if (rr < 32) sqA[rr] = s; else sqB[rr - 32] = s; }
    }
    __syncthreads();

    // ---- Gram 2x2 microtile with packed f32x2 FMA ----
    unsigned long long a00 = 0ull, a01 = 0ull, a10 = 0ull, a11 = 0ull;
    #pragma unroll
    for (int c4 = 0; c4 < 32; c4++) {
        ulonglong2 A0 = *(const ulonglong2*)&As[ty][c4 * 4];
        ulonglong2 A1 = *(const ulonglong2*)&As[ty + 16][c4 * 4];
        ulonglong2 B0 = *(const ulonglong2*)&Bs[tx][c4 * 4];
        ulonglong2 B1 = *(const ulonglong2*)&Bs[tx + 16][c4 * 4];
        fma2(a00, A0.x, B0.x); fma2(a00, A0.y, B0.y);
        fma2(a01, A0.x, B1.x); fma2(a01, A0.y, B1.y);
        fma2(a10, A1.x, B0.x); fma2(a10, A1.y, B0.y);
        fma2(a11, A1.x, B1.x); fma2(a11, A1.y, B1.y);
    }
    {
        float2 f00 = *(float2*)&a00, f01 = *(float2*)&a01;
        float2 f10 = *(float2*)&a10, f11 = *(float2*)&a11;
        float acc[2][2] = { { f00.x + f00.y, f01.x + f01.y },
                            { f10.x + f10.y, f11.x + f11.y } };
        const int rows[2] = { ty, ty + 16 };
        const int cols[2] = { tx, tx + 16 };
        #pragma unroll
        for (int a = 0; a < 2; a++) {
            int gr = by * TILE + rows[a];
            if (gr >= N) continue;
            #pragma unroll
            for (int b = 0; b < 2; b++) {
                int gc = bx * TILE + cols[b];
                if (gc >= N) continue;
                float v = (sqA[rows[a]] + sqB[cols[b]]) - 2.0f * acc[a][b];
                v = fmaxf(v, 0.0f);
                v = fmaxf(v, EPSV);
                g_d[gr * N + gc] = sqrtf(v);
            }
        }
    }

    // ---- software grid barrier (all blocks co-resident) ----
    __threadfence();
    __syncthreads();
    if (tid == 0) {
        atomicAdd(&g_bar, 1u);
        while (atomicAdd(&g_bar, 0u) < (unsigned)nblocks)
            __nanosleep(32);
    }
    __syncthreads();

    // ---- Phase 2: warp-per-row, row in registers ----
    const int bid = by * gridDim.x + bx;
    const int gw  = bid * (TPB / 32) + warp;
    float    wnum = 0.f;
    unsigned wcnt = 0u;

    if (gw < N) {
        const float* __restrict__ row = g_d + (size_t)gw * N;
        const int li = labs_s[gw];
        const int NR = (N + 31) >> 5;

        float v[NRMAX];
        bool  pos[NRMAX], neg[NRMAX];
        float mn = 1e30f, mx = -1e30f, mxneg = -1e30f;

        #pragma unroll
        for (int r = 0; r < NRMAX; r++) {
            int j = r * 32 + lane;
            bool val = (r < NR) && (j < N);
            v[r] = val ? row[j] : 0.f;
            int lj = val ? labs_s[j] : 0x7fffffff;
            pos[r] = val && (lj == li) && (j != gw);
            neg[r] = val && !pos[r];                 // negatives incl. diagonal
            if (val) { mn = fminf(mn, v[r]); mx = fmaxf(mx, v[r]); }
            if (neg[r]) mxneg = fmaxf(mxneg, v[r]);
        }
        #pragma unroll
        for (int o = 16; o > 0; o >>= 1) {
            mn    = fminf(mn,    __shfl_xor_sync(0xffffffffu, mn,    o));
            mx    = fmaxf(mx,    __shfl_xor_sync(0xffffffffu, mx,    o));
            mxneg = fmaxf(mxneg, __shfl_xor_sync(0xffffffffu, mxneg, o));
        }

        #pragma unroll
        for (int r = 0; r < NRMAX; r++) {
            unsigned bm = __ballot_sync(0xffffffffu, pos[r]);
            while (bm) {
                int b = __ffs(bm) - 1;
                bm &= bm - 1;
                float c = __shfl_sync(0xffffffffu, v[r], b);

                // succ = min { r_j : j negative, r_j > c }
                float succ = 1e30f;
                #pragma unroll
                for (int r2 = 0; r2 < NRMAX; r2++)
                    if (neg[r2] && v[r2] > c) succ = fminf(succ, v[r2]);
                #pragma unroll
                for (int o = 16; o > 0; o >>= 1)
                    succ = fminf(succ, __shfl_xor_sync(0xffffffffu, succ, o));

                if (lane == 0) {
                    float semi;
                    if (succ < 1e29f) {
                        float mn_dd = c - mx;                  // min_j fl(c - r_j)
                        semi = ((c - succ) - mn_dd) + mn_dd;   // masked max, exact rounding
                    } else {
                        float mx_dd = c - mn;                  // max_j fl(c - r_j)
                        semi = ((c - mxneg) - mx_dd) + mx_dd;  // masked min, exact rounding
                    }
                    wnum += fmaxf(semi + MARGINV, 0.f);
                    wcnt++;
                }
            }
        }
    }

    if (lane == 0 && wcnt) {
        atomicAdd(&g_num, wnum);
        atomicAdd(&g_den, wcnt);
    }

    // ---- ticket finisher ----
    __syncthreads();
    if (tid == 0) {
        __threadfence();
        unsigned tk = atomicAdd(&g_done, 1u);
        if (tk == (unsigned)(nblocks - 1)) {
            float    num = atomicAdd(&g_num, 0.f);
            unsigned den = atomicAdd(&g_den, 0u);
            out[0] = num / (float)den;
            g_num = 0.f; g_den = 0u; g_bar = 0u; g_done = 0u;   // replay reset
            __threadfence();
        }
    }
}

extern "C" void kernel_launch(void* const* d_in, const int* in_sizes, int n_in,
                              void* d_out, int out_size) {
    const float* emb = (const float*)d_in[0];
    const unsigned int* labs = (const unsigned int*)d_in[1];
    float* out = (float*)d_out;

    const int N = in_sizes[1];
    const int D = in_sizes[0] / N;
    const int G = (N + TILE - 1) / TILE;

    dim3 grid(G, G);
    triplet_one<<<grid, TPB>>>(emb, labs, out, N, D, G * G);
}

// round 9
// speedup vs baseline: 3.0557x; 1.0219x over previous
#include <cuda_runtime.h>
#include <cuda_bf16.h>

// TripletSemihardLoss — single launch, two phases + software grid barrier.
// Phase 1: 144 blocks (12x12) compute 32x32 distance-matrix tiles with a
//          2x2-microtile smem GEMM using packed fma.rn.f32x2.
// Phase 2: warp-per-anchor-row loss, row in registers, redux.sync reductions;
//          successor-query reconstruction of the reference's masked max/min.
// Grid <= #SMs -> all blocks co-resident -> spin barrier is safe.

#define EPSV    1e-4f
#define MARGINV 1.0f
#define TILE    32
#define TPB     256
#define MAXN    512
#define NRMAX   12          // 12 * 32 = 384 row elements in registers

__device__ float    g_d[MAXN * MAXN];
__device__ float    g_num;      // zero-init; finisher resets
__device__ unsigned g_den;
__device__ unsigned g_bar;
__device__ unsigned g_done;

__device__ __forceinline__ void fma2(unsigned long long& d,
                                     unsigned long long a,
                                     unsigned long long b) {
    // packed f32x2 FMA: d.lo += a.lo*b.lo ; d.hi += a.hi*b.hi  (SASS FFMA2)
    asm("fma.rn.f32x2 %0, %1, %2, %0;" : "+l"(d) : "l"(a), "l"(b));
}

// positive floats only: float order == uint-bit order
__device__ __forceinline__ float warp_min_pos(float v) {
    return __uint_as_float(__reduce_min_sync(0xffffffffu, __float_as_uint(v)));
}
__device__ __forceinline__ float warp_max_pos(float v) {
    return __uint_as_float(__reduce_max_sync(0xffffffffu, __float_as_uint(v)));
}

__global__ void __launch_bounds__(TPB, 1)
triplet_one(const float* __restrict__ emb,
            const unsigned int* __restrict__ labs,
            float* __restrict__ out,
            int N, int D, int nblocks) {
    __shared__ __align__(16) float As[TILE][132];   // 132-float stride: LDS.128
    __shared__ __align__(16) float Bs[TILE][132];   // phase-conflict-free
    __shared__ float sqA[TILE], sqB[TILE];
    __shared__ int   labs_s[MAXN];
    __shared__ int   s_is64;

    const int tid  = threadIdx.x;
    const int lane = tid & 31;
    const int warp = tid >> 5;
    const int tx   = tid & 15;          // col pair (tx, tx+16)
    const int ty   = tid >> 4;          // row pair (ty, ty+16)
    const int bx   = blockIdx.x;
    const int by   = blockIdx.y;

    // ---- issue tile LDGs first (hide cold-load latency) ----
    float4 va[4], vb[4];
    #pragma unroll
    for (int p = 0; p < 4; p++) {
        int e = p * TPB + tid;
        int r = e >> 5, gc = (e & 31) * 4;
        int ga = by * TILE + r, gb = bx * TILE + r;
        float4 z = make_float4(0.f, 0.f, 0.f, 0.f);
        va[p] = (ga < N && gc + 3 < D) ? __ldg((const float4*)(emb + (size_t)ga * D + gc)) : z;
        vb[p] = (gb < N && gc + 3 < D) ? __ldg((const float4*)(emb + (size_t)gb * D + gc)) : z;
    }

    // ---- label width detect, warp-parallel (int64 => odd LE words zero) ----
    if (warp == 0) {
        unsigned lw = (lane < 16) ? labs[lane] : 0u;
        unsigned oddnz = __ballot_sync(0xffffffffu, (lane < 16) && (lane & 1) && (lw != 0u));
        if (lane == 0) s_is64 = (oddnz == 0u) ? 1 : 0;
    }

    // ---- store tiles to smem ----
    #pragma unroll
    for (int p = 0; p < 4; p++) {
        int e = p * TPB + tid;
        int r = e >> 5, gc = (e & 31) * 4;
        *(float4*)&As[r][gc] = va[p];
        *(float4*)&Bs[r][gc] = vb[p];
    }
    __syncthreads();
    const int is64 = s_is64;

    // ---- label table fill (LDGs overlap with sq/GEMM below) ----
    for (int j = tid; j < N; j += TPB)
        labs_s[j] = (int)labs[is64 ? 2 * j : j];

    // ---- row squared norms: 8 warps x 8 rows ----
    #pragma unroll
    for (int q = 0; q < 8; q++) {
        int rr = warp * 8 + q;
        const float* src = (rr < 32) ? As[rr] : Bs[rr - 32];
        float s = 0.f;
        #pragma unroll
        for (int k = 0; k < 4; k++) {
            int c = lane + 32 * k;
            float v = (c < D) ? src[c] : 0.f;
            s = fmaf(v, v, s);
        }
        #pragma unroll
        for (int o = 16; o > 0; o >>= 1)
            s += __shfl_xor_sync(0xffffffffu, s, o);
        if (lane == 0) { if (rr < 32) sqA[rr] = s; else sqB[rr - 32] = s; }
    }
    __syncthreads();

    // ---- Gram 2x2 microtile with packed f32x2 FMA ----
    unsigned long long a00 = 0ull, a01 = 0ull, a10 = 0ull, a11 = 0ull;
    #pragma unroll
    for (int c4 = 0; c4 < 32; c4++) {
        ulonglong2 A0 = *(const ulonglong2*)&As[ty][c4 * 4];
        ulonglong2 A1 = *(const ulonglong2*)&As[ty + 16][c4 * 4];
        ulonglong2 B0 = *(const ulonglong2*)&Bs[tx][c4 * 4];
        ulonglong2 B1 = *(const ulonglong2*)&Bs[tx + 16][c4 * 4];
        fma2(a00, A0.x, B0.x); fma2(a00, A0.y, B0.y);
        fma2(a01, A0.x, B1.x); fma2(a01, A0.y, B1.y);
        fma2(a10, A1.x, B0.x); fma2(a10, A1.y, B0.y);
        fma2(a11, A1.x, B1.x); fma2(a11, A1.y, B1.y);
    }
    {
        float2 f00 = *(float2*)&a00, f01 = *(float2*)&a01;
        float2 f10 = *(float2*)&a10, f11 = *(float2*)&a11;
        float acc[2][2] = { { f00.x + f00.y, f01.x + f01.y },
                            { f10.x + f10.y, f11.x + f11.y } };
        const int rows[2] = { ty, ty + 16 };
        const int cols[2] = { tx, tx + 16 };
        #pragma unroll
        for (int a = 0; a < 2; a++) {
            int gr = by * TILE + rows[a];
            if (gr >= N) continue;
            #pragma unroll
            for (int b = 0; b < 2; b++) {
                int gc = bx * TILE + cols[b];
                if (gc >= N) continue;
                float v = (sqA[rows[a]] + sqB[cols[b]]) - 2.0f * acc[a][b];
                v = fmaxf(v, 0.0f);
                v = fmaxf(v, EPSV);
                g_d[gr * N + gc] = sqrtf(v);
            }
        }
    }

    // ---- software grid barrier (all blocks co-resident) ----
    __threadfence();
    __syncthreads();
    if (tid == 0) {
        atomicAdd(&g_bar, 1u);
        while (atomicAdd(&g_bar, 0u) < (unsigned)nblocks)
            __nanosleep(32);
    }
    __syncthreads();

    // ---- Phase 2: warp-per-row, row in registers, redux reductions ----
    const int bid = by * gridDim.x + bx;
    const int gw  = bid * (TPB / 32) + warp;
    float    wnum = 0.f;
    unsigned wcnt = 0u;

    if (gw < N) {
        const float* __restrict__ row = g_d + (size_t)gw * N;
        const int li = labs_s[gw];
        const int NR = (N + 31) >> 5;

        float v[NRMAX];
        bool  pos[NRMAX], neg[NRMAX];
        // positive-float-safe identities (all distances >= sqrt(EPS) > 0)
        float mn = 1e30f, mx = 0.0f, mxneg = 0.0f;

        #pragma unroll
        for (int r = 0; r < NRMAX; r++) {
            int j = r * 32 + lane;
            bool val = (r < NR) && (j < N);
            v[r] = val ? row[j] : 0.f;
            int lj = val ? labs_s[j] : 0x7fffffff;
            pos[r] = val && (lj == li) && (j != gw);
            neg[r] = val && !pos[r];                 // negatives incl. diagonal
            if (val) { mn = fminf(mn, v[r]); mx = fmaxf(mx, v[r]); }
            if (neg[r]) mxneg = fmaxf(mxneg, v[r]);
        }
        mn    = warp_min_pos(mn);
        mx    = warp_max_pos(mx);
        mxneg = warp_max_pos(mxneg);

        #pragma unroll
        for (int r = 0; r < NRMAX; r++) {
            unsigned bm = __ballot_sync(0xffffffffu, pos[r]);
            while (bm) {
                int b = __ffs(bm) - 1;
                bm &= bm - 1;
                float c = __shfl_sync(0xffffffffu, v[r], b);

                // succ = min { r_j : j negative, r_j > c } — tree of candidates
                float s0 = 1e30f, s1 = 1e30f, s2 = 1e30f, s3 = 1e30f;
                #pragma unroll
                for (int r2 = 0; r2 < NRMAX; r2 += 4) {
                    float c0 = (neg[r2 + 0] && v[r2 + 0] > c) ? v[r2 + 0] : 1e30f;
                    float c1 = (neg[r2 + 1] && v[r2 + 1] > c) ? v[r2 + 1] : 1e30f;
                    float c2 = (neg[r2 + 2] && v[r2 + 2] > c) ? v[r2 + 2] : 1e30f;
                    float c3 = (neg[r2 + 3] && v[r2 + 3] > c) ? v[r2 + 3] : 1e30f;
                    s0 = fminf(s0, c0); s1 = fminf(s1, c1);
                    s2 = fminf(s2, c2); s3 = fminf(s3, c3);
                }
                float succ = warp_min_pos(fminf(fminf(s0, s1), fminf(s2, s3)));

                if (lane == 0) {
                    float semi;
                    if (succ < 1e29f) {
                        float mn_dd = c - mx;                  // min_j fl(c - r_j)
                        semi = ((c - succ) - mn_dd) + mn_dd;   // masked max, exact rounding
                    } else {
                        float mx_dd = c - mn;                  // max_j fl(c - r_j)
                        semi = ((c - mxneg) - mx_dd) + mx_dd;  // masked min, exact rounding
                    }
                    wnum += fmaxf(semi + MARGINV, 0.f);
                    wcnt++;
                }
            }
        }
    }

    if (lane == 0 && wcnt) {
        atomicAdd(&g_num, wnum);
        atomicAdd(&g_den, wcnt);
    }

    // ---- ticket finisher ----
    __syncthreads();
    if (tid == 0) {
        __threadfence();
        unsigned tk = atomicAdd(&g_done, 1u);
        if (tk == (unsigned)(nblocks - 1)) {
            float    num = atomicAdd(&g_num, 0.f);
            unsigned den = atomicAdd(&g_den, 0u);
            out[0] = num / (float)den;
            g_num = 0.f; g_den = 0u; g_bar = 0u; g_done = 0u;   // replay reset
            __threadfence();
        }
    }
}

extern "C" void kernel_launch(void* const* d_in, const int* in_sizes, int n_in,
                              void* d_out, int out_size) {
    const float* emb = (const float*)d_in[0];
    const unsigned int* labs = (const unsigned int*)d_in[1];
    float* out = (float*)d_out;

    const int N = in_sizes[1];
    const int D = in_sizes[0] / N;
    const int G = (N + TILE - 1) / TILE;

    dim3 grid(G, G);
    triplet_one<<<grid, TPB>>>(emb, labs, out, N, D, G * G);
}

// round 10
// speedup vs baseline: 3.4080x; 1.1153x over previous
#include <cuda_runtime.h>
#include <cuda_bf16.h>

// TripletSemihardLoss — single launch, two phases + software grid barrier.
// Phase 1: 144 blocks (12x12), 32x32 distance tiles. Transposed smem tiles;
//          GEMM = per-lane B-column vector loads + warp-uniform A broadcasts
//          (halves smem crossbar traffic vs 2x2 microtile), packed fma.rn.f32x2.
// Phase 2: warp-per-anchor-row loss, row in registers, redux.sync reductions;
//          successor-query reconstruction of the reference's masked max/min.
// Grid <= #SMs -> all blocks co-resident -> spin barrier is safe.

#define EPSV    1e-4f
#define MARGINV 1.0f
#define TILE    32
#define TPB     256
#define MAXN    512
#define NRMAX   12          // 12 * 32 = 384 row elements in registers
#define PAD4    33          // float4 row stride of transposed tiles

__device__ float    g_d[MAXN * MAXN];
__device__ float    g_num;      // zero-init; finisher resets
__device__ unsigned g_den;
__device__ unsigned g_bar;
__device__ unsigned g_done;

__device__ __forceinline__ void fma2(unsigned long long& d,
                                     unsigned long long a,
                                     unsigned long long b) {
    // packed f32x2 FMA: d.lo += a.lo*b.lo ; d.hi += a.hi*b.hi  (SASS FFMA2)
    asm("fma.rn.f32x2 %0, %1, %2, %0;" : "+l"(d) : "l"(a), "l"(b));
}

// positive floats only: float order == uint-bit order
__device__ __forceinline__ float warp_min_pos(float v) {
    return __uint_as_float(__reduce_min_sync(0xffffffffu, __float_as_uint(v)));
}
__device__ __forceinline__ float warp_max_pos(float v) {
    return __uint_as_float(__reduce_max_sync(0xffffffffu, __float_as_uint(v)));
}

__global__ void __launch_bounds__(TPB, 1)
triplet_one(const float* __restrict__ emb,
            const unsigned int* __restrict__ labs,
            float* __restrict__ out,
            int N, int D, int nblocks) {
    __shared__ __align__(16) float4 Atr[32][PAD4];  // [c4][row] transposed
    __shared__ __align__(16) float4 Btr[32][PAD4];
    __shared__ float sqA_s[TILE], sqB_s[TILE];
    __shared__ int   labs_s[MAXN];
    __shared__ int   s_is64;

    const int tid  = threadIdx.x;
    const int lane = tid & 31;
    const int warp = tid >> 5;
    const int bx   = blockIdx.x;
    const int by   = blockIdx.y;

    // ---- issue tile LDGs first (hide cold-load latency) ----
    float4 va[4], vb[4];
    #pragma unroll
    for (int p = 0; p < 4; p++) {
        int e = p * TPB + tid;
        int r = e >> 5, gc = (e & 31) * 4;
        int ga = by * TILE + r, gb = bx * TILE + r;
        float4 z = make_float4(0.f, 0.f, 0.f, 0.f);
        va[p] = (ga < N && gc + 3 < D) ? __ldg((const float4*)(emb + (size_t)ga * D + gc)) : z;
        vb[p] = (gb < N && gc + 3 < D) ? __ldg((const float4*)(emb + (size_t)gb * D + gc)) : z;
    }

    // ---- label width detect, warp-parallel (int64 => odd LE words zero) ----
    if (warp == 0) {
        unsigned lw = (lane < 16) ? labs[lane] : 0u;
        unsigned oddnz = __ballot_sync(0xffffffffu, (lane < 16) && (lane & 1) && (lw != 0u));
        if (lane == 0) s_is64 = (oddnz == 0u) ? 1 : 0;
    }

    // ---- store tiles TRANSPOSED to smem ----
    #pragma unroll
    for (int p = 0; p < 4; p++) {
        int e = p * TPB + tid;
        int r = e >> 5, c4 = e & 31;
        Atr[c4][r] = va[p];
        Btr[c4][r] = vb[p];
    }
    __syncthreads();
    const int is64 = s_is64;

    // ---- label table fill (LDGs overlap with compute below) ----
    for (int j = tid; j < N; j += TPB)
        labs_s[j] = (int)labs[is64 ? 2 * j : j];

    // ---- sq norms: per-lane column sums, fma2-ordered (matches GEMM) ----
    if (warp < 2) {
        const float4 (*T)[PAD4] = (warp == 0) ? Atr : Btr;
        unsigned long long acc = 0ull;
        #pragma unroll
        for (int c4 = 0; c4 < 32; c4++) {
            ulonglong2 u = *(const ulonglong2*)&T[c4][lane];
            fma2(acc, u.x, u.x);
            fma2(acc, u.y, u.y);
        }
        float2 f = *(float2*)&acc;
        if (warp == 0) sqA_s[lane] = f.x + f.y;
        else           sqB_s[lane] = f.x + f.y;
    }

    // ---- GEMM: warp w -> rows 4w..4w+3; lane l -> column l ----
    unsigned long long acc[4] = {0ull, 0ull, 0ull, 0ull};
    #pragma unroll
    for (int c4 = 0; c4 < 32; c4++) {
        ulonglong2 b = *(const ulonglong2*)&Btr[c4][lane];       // vector, 4 wf
        #pragma unroll
        for (int i = 0; i < 4; i++) {
            ulonglong2 a = *(const ulonglong2*)&Atr[c4][4 * warp + i];  // broadcast
            fma2(acc[i], a.x, b.x);
            fma2(acc[i], a.y, b.y);
        }
    }
    __syncthreads();

    // ---- combine + write d tile (coalesced per row) ----
    #pragma unroll
    for (int i = 0; i < 4; i++) {
        int r  = 4 * warp + i;
        int gr = by * TILE + r;
        int gc = bx * TILE + lane;
        if (gr < N && gc < N) {
            float2 f = *(float2*)&acc[i];
            float g  = f.x + f.y;
            float v  = (sqA_s[r] + sqB_s[lane]) - 2.0f * g;
            v = fmaxf(v, 0.0f);
            v = fmaxf(v, EPSV);
            g_d[gr * N + gc] = sqrtf(v);
        }
    }

    // ---- software grid barrier (all blocks co-resident) ----
    __threadfence();
    __syncthreads();
    if (tid == 0) {
        atomicAdd(&g_bar, 1u);
        while (atomicAdd(&g_bar, 0u) < (unsigned)nblocks)
            __nanosleep(32);
    }
    __syncthreads();

    // ---- Phase 2: warp-per-row, row in registers, redux reductions ----
    const int bid = by * gridDim.x + bx;
    const int gw  = bid * (TPB / 32) + warp;
    float    wnum = 0.f;
    unsigned wcnt = 0u;

    if (gw < N) {
        const float* __restrict__ row = g_d + (size_t)gw * N;
        const int li = labs_s[gw];
        const int NR = (N + 31) >> 5;

        float v[NRMAX];
        bool  pos[NRMAX], neg[NRMAX];
        // positive-float-safe identities (all distances >= sqrt(EPS) > 0)
        float mn = 1e30f, mx = 0.0f, mxneg = 0.0f;

        #pragma unroll
        for (int r = 0; r < NRMAX; r++) {
            int j = r * 32 + lane;
            bool val = (r < NR) && (j < N);
            v[r] = val ? row[j] : 0.f;
            int lj = val ? labs_s[j] : 0x7fffffff;
            pos[r] = val && (lj == li) && (j != gw);
            neg[r] = val && !pos[r];                 // negatives incl. diagonal
            if (val) { mn = fminf(mn, v[r]); mx = fmaxf(mx, v[r]); }
            if (neg[r]) mxneg = fmaxf(mxneg, v[r]);
        }
        mn    = warp_min_pos(mn);
        mx    = warp_max_pos(mx);
        mxneg = warp_max_pos(mxneg);

        #pragma unroll
        for (int r = 0; r < NRMAX; r++) {
            unsigned bm = __ballot_sync(0xffffffffu, pos[r]);
            while (bm) {
                int b = __ffs(bm) - 1;
                bm &= bm - 1;
                float c = __shfl_sync(0xffffffffu, v[r], b);

                // succ = min { r_j : j negative, r_j > c } — tree of candidates
                float s0 = 1e30f, s1 = 1e30f, s2 = 1e30f, s3 = 1e30f;
                #pragma unroll
                for (int r2 = 0; r2 < NRMAX; r2 += 4) {
                    float c0 = (neg[r2 + 0] && v[r2 + 0] > c) ? v[r2 + 0] : 1e30f;
                    float c1 = (neg[r2 + 1] && v[r2 + 1] > c) ? v[r2 + 1] : 1e30f;
                    float c2 = (neg[r2 + 2] && v[r2 + 2] > c) ? v[r2 + 2] : 1e30f;
                    float c3 = (neg[r2 + 3] && v[r2 + 3] > c) ? v[r2 + 3] : 1e30f;
                    s0 = fminf(s0, c0); s1 = fminf(s1, c1);
                    s2 = fminf(s2, c2); s3 = fminf(s3, c3);
                }
                float succ = warp_min_pos(fminf(fminf(s0, s1), fminf(s2, s3)));

                if (lane == 0) {
                    float semi;
                    if (succ < 1e29f) {
                        float mn_dd = c - mx;                  // min_j fl(c - r_j)
                        semi = ((c - succ) - mn_dd) + mn_dd;   // masked max, exact rounding
                    } else {
                        float mx_dd = c - mn;                  // max_j fl(c - r_j)
                        semi = ((c - mxneg) - mx_dd) + mx_dd;  // masked min, exact rounding
                    }
                    wnum += fmaxf(semi + MARGINV, 0.f);
                    wcnt++;
                }
            }
        }
    }

    if (lane == 0 && wcnt) {
        atomicAdd(&g_num, wnum);
        atomicAdd(&g_den, wcnt);
    }

    // ---- ticket finisher ----
    __syncthreads();
    if (tid == 0) {
        __threadfence();
        unsigned tk = atomicAdd(&g_done, 1u);
        if (tk == (unsigned)(nblocks - 1)) {
            float    num = atomicAdd(&g_num, 0.f);
            unsigned den = atomicAdd(&g_den, 0u);
            out[0] = num / (float)den;
            g_num = 0.f; g_den = 0u; g_bar = 0u; g_done = 0u;   // replay reset
            __threadfence();
        }
    }
}

extern "C" void kernel_launch(void* const* d_in, const int* in_sizes, int n_in,
                              void* d_out, int out_size) {
    const float* emb = (const float*)d_in[0];
    const unsigned int* labs = (const unsigned int*)d_in[1];
    float* out = (float*)d_out;

    const int N = in_sizes[1];
    const int D = in_sizes[0] / N;
    const int G = (N + TILE - 1) / TILE;

    dim3 grid(G, G);
    triplet_one<<<grid, TPB>>>(emb, labs, out, N, D, G * G);
}

// round 11
// speedup vs baseline: 3.4232x; 1.0045x over previous
#include <cuda_runtime.h>
#include <cuda_bf16.h>

// TripletSemihardLoss — single launch, two phases + software grid barrier.
// Phase 1: 144 blocks (12x12), 512 threads: 32x32 distance tiles. Transposed
//          smem tiles; warp w -> rows {2w,2w+1}, lane -> column; packed
//          fma.rn.f32x2. Per-output accumulation order identical to prior round.
// Phase 2: warp-per-anchor-row loss (rows spread across blocks), row in
//          registers, redux.sync reductions; successor-query reconstruction.
// Grid <= #SMs -> all blocks co-resident -> spin barrier is safe.

#define EPSV    1e-4f
#define MARGINV 1.0f
#define TILE    32
#define TPB     512
#define NWARP   (TPB / 32)
#define MAXN    512
#define NRMAX   12          // 12 * 32 = 384 row elements in registers
#define PAD4    33          // float4 row stride of transposed tiles

__device__ float    g_d[MAXN * MAXN];
__device__ float    g_num;      // zero-init; finisher resets
__device__ unsigned g_den;
__device__ unsigned g_bar;
__device__ unsigned g_done;

__device__ __forceinline__ void fma2(unsigned long long& d,
                                     unsigned long long a,
                                     unsigned long long b) {
    // packed f32x2 FMA: d.lo += a.lo*b.lo ; d.hi += a.hi*b.hi  (SASS FFMA2)
    asm("fma.rn.f32x2 %0, %1, %2, %0;" : "+l"(d) : "l"(a), "l"(b));
}

// positive floats only: float order == uint-bit order
__device__ __forceinline__ float warp_min_pos(float v) {
    return __uint_as_float(__reduce_min_sync(0xffffffffu, __float_as_uint(v)));
}
__device__ __forceinline__ float warp_max_pos(float v) {
    return __uint_as_float(__reduce_max_sync(0xffffffffu, __float_as_uint(v)));
}

__global__ void __launch_bounds__(TPB, 1)
triplet_one(const float* __restrict__ emb,
            const unsigned int* __restrict__ labs,
            float* __restrict__ out,
            int N, int D, int nblocks) {
    __shared__ __align__(16) float4 Atr[32][PAD4];  // [c4][row] transposed
    __shared__ __align__(16) float4 Btr[32][PAD4];
    __shared__ float sqA_s[TILE], sqB_s[TILE];
    __shared__ int   labs_s[MAXN];
    __shared__ int   s_is64;

    const int tid  = threadIdx.x;
    const int lane = tid & 31;
    const int warp = tid >> 5;
    const int bx   = blockIdx.x;
    const int by   = blockIdx.y;

    // ---- issue tile LDGs first (hide cold-load latency) ----
    float4 va[2], vb[2];
    #pragma unroll
    for (int p = 0; p < 2; p++) {
        int e = p * TPB + tid;
        int r = e >> 5, gc = (e & 31) * 4;
        int ga = by * TILE + r, gb = bx * TILE + r;
        float4 z = make_float4(0.f, 0.f, 0.f, 0.f);
        va[p] = (ga < N && gc + 3 < D) ? __ldg((const float4*)(emb + (size_t)ga * D + gc)) : z;
        vb[p] = (gb < N && gc + 3 < D) ? __ldg((const float4*)(emb + (size_t)gb * D + gc)) : z;
    }

    // ---- label width detect, warp-parallel (int64 => odd LE words zero) ----
    if (warp == 0) {
        unsigned lw = (lane < 16) ? labs[lane] : 0u;
        unsigned oddnz = __ballot_sync(0xffffffffu, (lane < 16) && (lane & 1) && (lw != 0u));
        if (lane == 0) s_is64 = (oddnz == 0u) ? 1 : 0;
    }

    // ---- store tiles TRANSPOSED to smem ----
    #pragma unroll
    for (int p = 0; p < 2; p++) {
        int e = p * TPB + tid;
        int r = e >> 5, c4 = e & 31;
        Atr[c4][r] = va[p];
        Btr[c4][r] = vb[p];
    }
    __syncthreads();
    const int is64 = s_is64;

    // ---- label table fill (LDGs overlap with compute below) ----
    for (int j = tid; j < N; j += TPB)
        labs_s[j] = (int)labs[is64 ? 2 * j : j];

    // ---- sq norms: per-lane column sums, fma2-ordered (matches GEMM) ----
    if (warp < 2) {
        const float4 (*T)[PAD4] = (warp == 0) ? Atr : Btr;
        unsigned long long acc = 0ull;
        #pragma unroll
        for (int c4 = 0; c4 < 32; c4++) {
            ulonglong2 u = *(const ulonglong2*)&T[c4][lane];
            fma2(acc, u.x, u.x);
            fma2(acc, u.y, u.y);
        }
        float2 f = *(float2*)&acc;
        if (warp == 0) sqA_s[lane] = f.x + f.y;
        else           sqB_s[lane] = f.x + f.y;
    }

    // ---- GEMM: warp w -> rows {2w, 2w+1}; lane l -> column l ----
    unsigned long long acc0 = 0ull, acc1 = 0ull;
    #pragma unroll
    for (int c4 = 0; c4 < 32; c4++) {
        ulonglong2 b  = *(const ulonglong2*)&Btr[c4][lane];            // vector
        ulonglong2 a0 = *(const ulonglong2*)&Atr[c4][2 * warp];        // broadcast
        ulonglong2 a1 = *(const ulonglong2*)&Atr[c4][2 * warp + 1];
        fma2(acc0, a0.x, b.x); fma2(acc0, a0.y, b.y);
        fma2(acc1, a1.x, b.x); fma2(acc1, a1.y, b.y);
    }
    __syncthreads();

    // ---- combine + write d tile (coalesced per row) ----
    {
        unsigned long long accs[2] = { acc0, acc1 };
        #pragma unroll
        for (int i = 0; i < 2; i++) {
            int r  = 2 * warp + i;
            int gr = by * TILE + r;
            int gc = bx * TILE + lane;
            if (gr < N && gc < N) {
                float2 f = *(float2*)&accs[i];
                float g  = f.x + f.y;
                float v  = (sqA_s[r] + sqB_s[lane]) - 2.0f * g;
                v = fmaxf(v, 0.0f);
                v = fmaxf(v, EPSV);
                g_d[gr * N + gc] = sqrtf(v);
            }
        }
    }

    // ---- software grid barrier (all blocks co-resident) ----
    __threadfence();
    __syncthreads();
    if (tid == 0) {
        atomicAdd(&g_bar, 1u);
        while (atomicAdd(&g_bar, 0u) < (unsigned)nblocks)
            __nanosleep(32);
    }
    __syncthreads();

    // ---- Phase 2: warp-per-row, rows spread across blocks ----
    const int bid = by * gridDim.x + bx;
    const int gw  = bid + nblocks * warp;   // block handles <=3 rows (warps 0..2)
    float    wnum = 0.f;
    unsigned wcnt = 0u;

    if (gw < N) {
        const float* __restrict__ row = g_d + (size_t)gw * N;
        const int li = labs_s[gw];
        const int NR = (N + 31) >> 5;

        float v[NRMAX];
        bool  pos[NRMAX], neg[NRMAX];
        // positive-float-safe identities (all distances >= sqrt(EPS) > 0)
        float mn = 1e30f, mx = 0.0f, mxneg = 0.0f;

        #pragma unroll
        for (int r = 0; r < NRMAX; r++) {
            int j = r * 32 + lane;
            bool val = (r < NR) && (j < N);
            v[r] = val ? row[j] : 0.f;
            int lj = val ? labs_s[j] : 0x7fffffff;
            pos[r] = val && (lj == li) && (j != gw);
            neg[r] = val && !pos[r];                 // negatives incl. diagonal
            if (val) { mn = fminf(mn, v[r]); mx = fmaxf(mx, v[r]); }
            if (neg[r]) mxneg = fmaxf(mxneg, v[r]);
        }
        mn    = warp_min_pos(mn);
        mx    = warp_max_pos(mx);
        mxneg = warp_max_pos(mxneg);

        #pragma unroll
        for (int r = 0; r < NRMAX; r++) {
            unsigned bm = __ballot_sync(0xffffffffu, pos[r]);
            while (bm) {
                int b = __ffs(bm) - 1;
                bm &= bm - 1;
                float c = __shfl_sync(0xffffffffu, v[r], b);

                // succ = min { r_j : j negative, r_j > c } — tree of candidates
                float s0 = 1e30f, s1 = 1e30f, s2 = 1e30f, s3 = 1e30f;
                #pragma unroll
                for (int r2 = 0; r2 < NRMAX; r2 += 4) {
                    float c0 = (neg[r2 + 0] && v[r2 + 0] > c) ? v[r2 + 0] : 1e30f;
                    float c1 = (neg[r2 + 1] && v[r2 + 1] > c) ? v[r2 + 1] : 1e30f;
                    float c2 = (neg[r2 + 2] && v[r2 + 2] > c) ? v[r2 + 2] : 1e30f;
                    float c3 = (neg[r2 + 3] && v[r2 + 3] > c) ? v[r2 + 3] : 1e30f;
                    s0 = fminf(s0, c0); s1 = fminf(s1, c1);
                    s2 = fminf(s2, c2); s3 = fminf(s3, c3);
                }
                float succ = warp_min_pos(fminf(fminf(s0, s1), fminf(s2, s3)));

                if (lane == 0) {
                    float semi;
                    if (succ < 1e29f) {
                        float mn_dd = c - mx;                  // min_j fl(c - r_j)
                        semi = ((c - succ) - mn_dd) + mn_dd;   // masked max, exact rounding
                    } else {
                        float mx_dd = c - mn;                  // max_j fl(c - r_j)
                        semi = ((c - mxneg) - mx_dd) + mx_dd;  // masked min, exact rounding
                    }
                    wnum += fmaxf(semi + MARGINV, 0.f);
                    wcnt++;
                }
            }
        }
    }

    if (lane == 0 && wcnt) {
        atomicAdd(&g_num, wnum);
        atomicAdd(&g_den, wcnt);
    }

    // ---- ticket finisher ----
    __syncthreads();
    if (tid == 0) {
        __threadfence();
        unsigned tk = atomicAdd(&g_done, 1u);
        if (tk == (unsigned)(nblocks - 1)) {
            float    num = atomicAdd(&g_num, 0.f);
            unsigned den = atomicAdd(&g_den, 0u);
            out[0] = num / (float)den;
            g_num = 0.f; g_den = 0u; g_bar = 0u; g_done = 0u;   // replay reset
            __threadfence();
        }
    }
}

extern "C" void kernel_launch(void* const* d_in, const int* in_sizes, int n_in,
                              void* d_out, int out_size) {
    const float* emb = (const float*)d_in[0];
    const unsigned int* labs = (const unsigned int*)d_in[1];
    float* out = (float*)d_out;

    const int N = in_sizes[1];
    const int D = in_sizes[0] / N;
    const int G = (N + TILE - 1) / TILE;

    dim3 grid(G, G);
    triplet_one<<<grid, TPB>>>(emb, labs, out, N, D, G * G);
}